// round 1
// baseline (speedup 1.0000x reference)
#include <cuda_runtime.h>
#include <math.h>

#define NB   8
#define EE   256
#define LL   64
#define SS   4096
#define QKV  768

// ---------------- scratch (static device allocations only) ----------------
__device__ float g_Y[NB * QKV * SS];      // [n][e][s] = qkv conv output; viewed as [n][s][768]
__device__ float g_qland[NB * LL * EE];
__device__ float g_kland[NB * LL * EE];
__device__ float g_S1[NB * SS * LL];      // [n][i][j]
__device__ float g_pmax[NB * 8 * LL];
__device__ float g_psum[NB * 8 * LL];
__device__ float g_m[NB * LL];
__device__ float g_sinv[NB * LL];
__device__ float g_S3[NB * LL * SS];      // [n][j][s]
__device__ float g_T3p[NB * 32 * LL * EE];
__device__ float g_T3[NB * LL * EE];
__device__ float g_M2s[NB * LL * EE];
__device__ float g_O[NB * SS * EE];       // [n][i][e]; viewed as [n][256][4096] for final gemm

// ---------------- generic 128x128 SGEMM + bias, batched over z ----------------
// C[n][m][s] = sum_k A[m][k] * B[n][k][s] + bias[m]
__global__ __launch_bounds__(256) void sgemm_bias_k(
    const float* __restrict__ A, const float* __restrict__ B,
    float* __restrict__ C, const float* __restrict__ bias,
    int M, int N, int K, long bStride, long cStride)
{
    __shared__ float As[8][128];
    __shared__ float Bs[8][128];
    const int n = blockIdx.z;
    const float* Bn = B + (long)n * bStride;
    float* Cn = C + (long)n * cStride;
    const int tM = blockIdx.y * 128;
    const int tN = blockIdx.x * 128;
    const int tid = threadIdx.x;
    const int aRow = tid >> 1, aCol = (tid & 1) * 4;
    const int bRow = tid >> 5, bCol = (tid & 31) * 4;
    const int tm = (tid >> 4) * 8, tn = (tid & 15) * 8;

    float acc[8][8];
#pragma unroll
    for (int i = 0; i < 8; i++)
#pragma unroll
        for (int j = 0; j < 8; j++) acc[i][j] = 0.f;

    for (int k0 = 0; k0 < K; k0 += 8) {
        float4 a4 = *(const float4*)(A + (long)(tM + aRow) * K + k0 + aCol);
        As[aCol + 0][aRow] = a4.x; As[aCol + 1][aRow] = a4.y;
        As[aCol + 2][aRow] = a4.z; As[aCol + 3][aRow] = a4.w;
        float4 b4 = *(const float4*)(Bn + (long)(k0 + bRow) * N + tN + bCol);
        *(float4*)&Bs[bRow][bCol] = b4;
        __syncthreads();
#pragma unroll
        for (int kk = 0; kk < 8; kk++) {
            float ra[8], rb[8];
            *(float4*)&ra[0] = *(const float4*)&As[kk][tm];
            *(float4*)&ra[4] = *(const float4*)&As[kk][tm + 4];
            *(float4*)&rb[0] = *(const float4*)&Bs[kk][tn];
            *(float4*)&rb[4] = *(const float4*)&Bs[kk][tn + 4];
#pragma unroll
            for (int i = 0; i < 8; i++)
#pragma unroll
                for (int j = 0; j < 8; j++) acc[i][j] += ra[i] * rb[j];
        }
        __syncthreads();
    }
#pragma unroll
    for (int i = 0; i < 8; i++) {
        float bi = bias[tM + tm + i];
        float4 o0 = make_float4(acc[i][0] + bi, acc[i][1] + bi, acc[i][2] + bi, acc[i][3] + bi);
        float4 o1 = make_float4(acc[i][4] + bi, acc[i][5] + bi, acc[i][6] + bi, acc[i][7] + bi);
        *(float4*)(Cn + (long)(tM + tm + i) * N + tN + tn) = o0;
        *(float4*)(Cn + (long)(tM + tm + i) * N + tN + tn + 4) = o1;
    }
}

// ---------------- landmarks: mean of 64 rows / scale(=64) => sum/4096 ----------------
__global__ void landmarks_k()
{
    int n = blockIdx.x, l = blockIdx.y, e = threadIdx.x;
    const float* base = g_Y + (long)n * QKV * SS;
    float aq = 0.f, ak = 0.f;
#pragma unroll 4
    for (int r = 0; r < 64; r++) {
        long off = (long)(l * 64 + r) * QKV;
        aq += base[off + e];
        ak += base[off + 256 + e];
    }
    g_qland[(n * LL + l) * EE + e] = aq * (1.f / 4096.f);
    g_kland[(n * LL + l) * EE + e] = ak * (1.f / 4096.f);
}

// ---------------- S1[i][j] = q[i,:] . kland[j,:]  (64i x 64j tile) ----------------
__global__ __launch_bounds__(256) void s1_gemm_k()
{
    __shared__ float Qs[32][64];
    __shared__ float Ks[32][64];
    int n = blockIdx.y;
    int i0 = blockIdx.x * 64;
    const float* qb = g_Y + (long)n * QKV * SS;       // q[i][e] = qb[i*768+e]
    const float* kl = g_kland + n * LL * EE;
    int tid = threadIdx.x;
    int ti = tid >> 4, tj = tid & 15;
    int lr = tid >> 3;            // 0..31
    int lc = (tid & 7) * 4;       // 0..28
    float acc[4][4];
#pragma unroll
    for (int a = 0; a < 4; a++)
#pragma unroll
        for (int b = 0; b < 4; b++) acc[a][b] = 0.f;

    for (int e0 = 0; e0 < 256; e0 += 32) {
#pragma unroll
        for (int p = 0; p < 2; p++) {
            int row = lr + p * 32;
            float4 v = *(const float4*)(qb + (long)(i0 + row) * QKV + e0 + lc);
            Qs[lc + 0][row] = v.x; Qs[lc + 1][row] = v.y;
            Qs[lc + 2][row] = v.z; Qs[lc + 3][row] = v.w;
            float4 w = *(const float4*)(kl + row * EE + e0 + lc);
            Ks[lc + 0][row] = w.x; Ks[lc + 1][row] = w.y;
            Ks[lc + 2][row] = w.z; Ks[lc + 3][row] = w.w;
        }
        __syncthreads();
#pragma unroll
        for (int kk = 0; kk < 32; kk++) {
            float4 a = *(const float4*)&Qs[kk][ti * 4];
            float4 b = *(const float4*)&Ks[kk][tj * 4];
            float ra[4] = {a.x, a.y, a.z, a.w};
            float rb[4] = {b.x, b.y, b.z, b.w};
#pragma unroll
            for (int r = 0; r < 4; r++)
#pragma unroll
                for (int c = 0; c < 4; c++) acc[r][c] += ra[r] * rb[c];
        }
        __syncthreads();
    }
#pragma unroll
    for (int r = 0; r < 4; r++) {
        float4 o = make_float4(acc[r][0], acc[r][1], acc[r][2], acc[r][3]);
        *(float4*)(g_S1 + ((long)n * SS + i0 + ti * 4 + r) * 64 + tj * 4) = o;
    }
}

// ---------------- column softmax stats for S1 (over 4096 rows) ----------------
__global__ void colstats_part_k()
{
    __shared__ float sm[4][64];
    int stripe = blockIdx.x, n = blockIdx.y;
    int tid = threadIdx.x;
    int j = tid & 63, g = tid >> 6;
    const float* S = g_S1 + (long)n * SS * 64;
    float m = -1e30f;
    for (int i = stripe * 512 + g; i < stripe * 512 + 512; i += 4)
        m = fmaxf(m, S[(long)i * 64 + j]);
    sm[g][j] = m;
    __syncthreads();
    float mm = fmaxf(fmaxf(sm[0][j], sm[1][j]), fmaxf(sm[2][j], sm[3][j]));
    float s = 0.f;
    for (int i = stripe * 512 + g; i < stripe * 512 + 512; i += 4)
        s += expf(S[(long)i * 64 + j] - mm);
    __syncthreads();
    sm[g][j] = s;
    __syncthreads();
    if (g == 0) {
        float ss = sm[0][j] + sm[1][j] + sm[2][j] + sm[3][j];
        g_pmax[(n * 8 + stripe) * 64 + j] = mm;
        g_psum[(n * 8 + stripe) * 64 + j] = ss;
    }
}

__global__ void colstats_comb_k()
{
    int n = blockIdx.x, j = threadIdx.x;
    float m = -1e30f;
#pragma unroll
    for (int c = 0; c < 8; c++) m = fmaxf(m, g_pmax[(n * 8 + c) * 64 + j]);
    float s = 0.f;
#pragma unroll
    for (int c = 0; c < 8; c++)
        s += g_psum[(n * 8 + c) * 64 + j] * expf(g_pmax[(n * 8 + c) * 64 + j] - m);
    g_m[n * 64 + j] = m;
    g_sinv[n * 64 + j] = 1.f / s;
}

// ---------------- S3[j][s] = qland[j,:] . k[s,:]  (64j x 64s tile) ----------------
__global__ __launch_bounds__(256) void s3_gemm_k()
{
    __shared__ float Qs[32][64];   // [e][j]
    __shared__ float Ks[32][64];   // [e][s]
    int n = blockIdx.y;
    int s0 = blockIdx.x * 64;
    const float* ql = g_qland + n * LL * EE;
    const float* kb = g_Y + (long)n * QKV * SS + 256;  // k[s][e] = kb[s*768+e]
    int tid = threadIdx.x;
    int ti = tid >> 4, tj = tid & 15;
    int lr = tid >> 3;
    int lc = (tid & 7) * 4;
    float acc[4][4];
#pragma unroll
    for (int a = 0; a < 4; a++)
#pragma unroll
        for (int b = 0; b < 4; b++) acc[a][b] = 0.f;

    for (int e0 = 0; e0 < 256; e0 += 32) {
#pragma unroll
        for (int p = 0; p < 2; p++) {
            int row = lr + p * 32;
            float4 v = *(const float4*)(ql + row * EE + e0 + lc);
            Qs[lc + 0][row] = v.x; Qs[lc + 1][row] = v.y;
            Qs[lc + 2][row] = v.z; Qs[lc + 3][row] = v.w;
            float4 w = *(const float4*)(kb + (long)(s0 + row) * QKV + e0 + lc);
            Ks[lc + 0][row] = w.x; Ks[lc + 1][row] = w.y;
            Ks[lc + 2][row] = w.z; Ks[lc + 3][row] = w.w;
        }
        __syncthreads();
#pragma unroll
        for (int kk = 0; kk < 32; kk++) {
            float4 a = *(const float4*)&Qs[kk][ti * 4];
            float4 b = *(const float4*)&Ks[kk][tj * 4];
            float ra[4] = {a.x, a.y, a.z, a.w};
            float rb[4] = {b.x, b.y, b.z, b.w};
#pragma unroll
            for (int r = 0; r < 4; r++)
#pragma unroll
                for (int c = 0; c < 4; c++) acc[r][c] += ra[r] * rb[c];
        }
        __syncthreads();
    }
#pragma unroll
    for (int r = 0; r < 4; r++) {
        float4 o = make_float4(acc[r][0], acc[r][1], acc[r][2], acc[r][3]);
        *(float4*)(g_S3 + ((long)n * LL + ti * 4 + r) * SS + s0 + tj * 4) = o;
    }
}

// ---------------- softmax over landmark dim (64) per column of S3 ----------------
__global__ void softmax_s3_k()
{
    int n = blockIdx.y;
    int s = blockIdx.x * 256 + threadIdx.x;
    float* S = g_S3 + (long)n * LL * SS;
    float v[64];
    float m = -1e30f;
#pragma unroll
    for (int j = 0; j < 64; j++) { v[j] = S[(long)j * SS + s]; m = fmaxf(m, v[j]); }
    float sum = 0.f;
#pragma unroll
    for (int j = 0; j < 64; j++) { v[j] = expf(v[j] - m); sum += v[j]; }
    float r = 1.f / sum;
#pragma unroll
    for (int j = 0; j < 64; j++) S[(long)j * SS + s] = v[j] * r;
}

// ---------------- T3 = k3 @ v, split-K over 32 chunks of 128 columns ----------------
__global__ __launch_bounds__(256) void t3_splitk_k()
{
    __shared__ float As[16][64];    // [sc][j]
    __shared__ float Vs[16][256];   // [sc][e]
    int ch = blockIdx.x, n = blockIdx.y;
    int s0 = ch * 128;
    const float* S = g_S3 + (long)n * LL * SS;
    const float* vb = g_Y + (long)n * QKV * SS + 512;
    int tid = threadIdx.x;
    int j0 = (tid >> 5) * 8, e0 = (tid & 31) * 8;
    int ajr = tid >> 2;           // 0..63
    int asc = (tid & 3) * 4;      // 0..12
    int vr = tid >> 4;            // 0..15
    int vc = (tid & 15) * 4;      // 0..60

    float acc[8][8];
#pragma unroll
    for (int a = 0; a < 8; a++)
#pragma unroll
        for (int b = 0; b < 8; b++) acc[a][b] = 0.f;

    for (int sb = 0; sb < 128; sb += 16) {
        float4 a = *(const float4*)(S + (long)ajr * SS + s0 + sb + asc);
        As[asc + 0][ajr] = a.x; As[asc + 1][ajr] = a.y;
        As[asc + 2][ajr] = a.z; As[asc + 3][ajr] = a.w;
#pragma unroll
        for (int p = 0; p < 4; p++)
            *(float4*)&Vs[vr][vc + p * 64] =
                *(const float4*)(vb + (long)(s0 + sb + vr) * QKV + vc + p * 64);
        __syncthreads();
#pragma unroll
        for (int sc = 0; sc < 16; sc++) {
            float a_[8];
#pragma unroll
            for (int r = 0; r < 8; r++) a_[r] = As[sc][j0 + r];
            float4 b0 = *(const float4*)&Vs[sc][e0];
            float4 b1 = *(const float4*)&Vs[sc][e0 + 4];
            float rb[8] = {b0.x, b0.y, b0.z, b0.w, b1.x, b1.y, b1.z, b1.w};
#pragma unroll
            for (int r = 0; r < 8; r++)
#pragma unroll
                for (int c = 0; c < 8; c++) acc[r][c] += a_[r] * rb[c];
        }
        __syncthreads();
    }
    float* dst = g_T3p + (long)(n * 32 + ch) * 64 * 256;
#pragma unroll
    for (int r = 0; r < 8; r++) {
        float4 o0 = make_float4(acc[r][0], acc[r][1], acc[r][2], acc[r][3]);
        float4 o1 = make_float4(acc[r][4], acc[r][5], acc[r][6], acc[r][7]);
        *(float4*)(dst + (j0 + r) * 256 + e0) = o0;
        *(float4*)(dst + (j0 + r) * 256 + e0 + 4) = o1;
    }
}

__global__ void t3_reduce_k()
{
    int idx = blockIdx.x * 256 + threadIdx.x;   // 0..131071
    int n = idx >> 14;
    int r = idx & 16383;
    const float* p = g_T3p + (long)n * 32 * 16384 + r;
    float s = 0.f;
#pragma unroll
    for (int c = 0; c < 32; c++) s += p[(long)c * 16384];
    g_T3[idx] = s;
}

// ---------------- 64x64 smem matmul helper ----------------
__device__ __forceinline__ void mm64(float* D, const float* A, const float* B, int tid)
{
    int r = (tid >> 5) * 2;
    int c = (tid & 31) * 2;
    float d00 = 0.f, d01 = 0.f, d10 = 0.f, d11 = 0.f;
#pragma unroll 16
    for (int k = 0; k < 64; k++) {
        float a0 = A[r * 64 + k], a1 = A[(r + 1) * 64 + k];
        float b0 = B[k * 64 + c], b1 = B[k * 64 + c + 1];
        d00 += a0 * b0; d01 += a0 * b1; d10 += a1 * b0; d11 += a1 * b1;
    }
    D[r * 64 + c] = d00; D[r * 64 + c + 1] = d01;
    D[(r + 1) * 64 + c] = d10; D[(r + 1) * 64 + c + 1] = d11;
    __syncthreads();
}

// ---------------- k2 softmax + Newton-Schulz inverse + M2s (one block / batch) ----------------
#define K2INV_SMEM_FLOATS (4096 * 5 + 2048 * 2 + 192)
__global__ __launch_bounds__(1024) void k2inv_k()
{
    extern __shared__ float sm[];
    float* K2 = sm;
    float* Vv = sm + 4096;
    float* BA = sm + 8192;
    float* BB = sm + 12288;
    float* BC = sm + 16384;
    float* QL = sm + 20480;   // [i][ec] 64x32
    float* KT = sm + 22528;   // [ec][j] 32x64
    float* red = sm + 24576;  // 192

    int n = blockIdx.x;
    int tid = threadIdx.x;
    const float* ql = g_qland + n * 16384;
    const float* kl = g_kland + n * 16384;

    // S2 = qland @ kland^T
    float accS[4] = {0.f, 0.f, 0.f, 0.f};
    for (int e0 = 0; e0 < 256; e0 += 32) {
#pragma unroll
        for (int p = 0; p < 2; p++) {
            int t = tid + p * 1024;
            int r = t >> 5, c = t & 31;
            QL[r * 32 + c] = ql[r * 256 + e0 + c];
            KT[c * 64 + r] = kl[r * 256 + e0 + c];
        }
        __syncthreads();
#pragma unroll
        for (int p = 0; p < 4; p++) {
            int t = tid + p * 1024;
            int i = t >> 6, j = t & 63;
            float a = 0.f;
#pragma unroll
            for (int ec = 0; ec < 32; ec++) a += QL[i * 32 + ec] * KT[ec * 64 + j];
            accS[p] += a;
        }
        __syncthreads();
    }
#pragma unroll
    for (int p = 0; p < 4; p++) K2[tid + p * 1024] = accS[p];
    __syncthreads();

    // column softmax (over i)
    if (tid < 64) {
        int j = tid;
        float m = -1e30f;
        for (int i = 0; i < 64; i++) m = fmaxf(m, K2[i * 64 + j]);
        float s = 0.f;
        for (int i = 0; i < 64; i++) s += expf(K2[i * 64 + j] - m);
        red[j] = m; red[64 + j] = 1.f / s;
    }
    __syncthreads();
#pragma unroll
    for (int p = 0; p < 4; p++) {
        int t = tid + p * 1024;
        int j = t & 63;
        K2[t] = expf(K2[t] - red[j]) * red[64 + j];
    }
    __syncthreads();

    // V0 (max col abs-sum) and VI (max row abs-sum)
    if (tid < 64) {
        int i = tid;
        float rs = 0.f, cs = 0.f;
        for (int j = 0; j < 64; j++) { rs += fabsf(K2[i * 64 + j]); cs += fabsf(K2[j * 64 + i]); }
        red[i] = rs; red[64 + i] = cs;
    }
    __syncthreads();
    if (tid == 0) {
        float vi = 0.f, v0 = 0.f;
        for (int t = 0; t < 64; t++) { vi = fmaxf(vi, red[t]); v0 = fmaxf(v0, red[64 + t]); }
        red[128] = 1.f / (v0 * vi);
    }
    __syncthreads();
    float isc = red[128];
#pragma unroll
    for (int p = 0; p < 4; p++) {
        int t = tid + p * 1024;
        int a = t >> 6, b = t & 63;
        Vv[t] = K2[b * 64 + a] * isc;
    }
    __syncthreads();

    // 6 Newton-Schulz iterations: V = 0.25 V (13I - KV(15I - KV(7I - KV)))
    for (int it = 0; it < 6; it++) {
        mm64(BA, K2, Vv, tid);      // KV
        mm64(BB, BA, BA, tid);      // KV^2
#pragma unroll
        for (int p = 0; p < 4; p++) {
            int t = tid + p * 1024;
            float d = ((t >> 6) == (t & 63)) ? 15.f : 0.f;
            BB[t] = d - 7.f * BA[t] + BB[t];     // B2 = 15I - (7KV - KV^2)
        }
        __syncthreads();
        mm64(BC, BA, BB, tid);      // KV @ B2
#pragma unroll
        for (int p = 0; p < 4; p++) {
            int t = tid + p * 1024;
            float d = ((t >> 6) == (t & 63)) ? 13.f : 0.f;
            BC[t] = d - BC[t];                    // D = 13I - ...
        }
        __syncthreads();
        mm64(BB, Vv, BC, tid);      // V @ D
#pragma unroll
        for (int p = 0; p < 4; p++) {
            int t = tid + p * 1024;
            Vv[t] = 0.25f * BB[t];
        }
        __syncthreads();
    }

    // M2s = (k2_inv @ T3) * (1/colsum_j)
    const float* T3 = g_T3 + n * 16384;
    for (int t = tid; t < 16384; t += 1024) {
        int j = t >> 8, e = t & 255;
        float a = 0.f;
#pragma unroll
        for (int k = 0; k < 64; k++) a += Vv[j * 64 + k] * T3[k * 256 + e];
        g_M2s[n * 16384 + t] = a * g_sinv[n * 64 + j];
    }
}

// ---------------- out = exp(S1 - m) @ M2s + v  (64 rows x 256 cols per block) ----------------
#define OUT_SMEM_FLOATS (16384 + 4096 + 64)
__global__ __launch_bounds__(256) void out_gemm_k()
{
    extern __shared__ float sm[];
    float* M2 = sm;           // 64x256
    float* P  = sm + 16384;   // 64x64
    float* ms = sm + 20480;   // 64
    int n = blockIdx.y;
    int i0g = blockIdx.x * 64;
    int tid = threadIdx.x;

    for (int t = tid * 4; t < 16384; t += 1024)
        *(float4*)&M2[t] = *(const float4*)(g_M2s + n * 16384 + t);
    if (tid < 64) ms[tid] = g_m[n * 64 + tid];
    __syncthreads();

    {
        int r = tid >> 2, c0 = (tid & 3) * 16;
        const float* S = g_S1 + ((long)n * SS + i0g + r) * 64 + c0;
#pragma unroll
        for (int t = 0; t < 16; t += 4) {
            float4 v = *(const float4*)(S + t);
            P[r * 64 + c0 + t + 0] = expf(v.x - ms[c0 + t + 0]);
            P[r * 64 + c0 + t + 1] = expf(v.y - ms[c0 + t + 1]);
            P[r * 64 + c0 + t + 2] = expf(v.z - ms[c0 + t + 2]);
            P[r * 64 + c0 + t + 3] = expf(v.w - ms[c0 + t + 3]);
        }
    }
    __syncthreads();

    int ir = (tid >> 5) * 8, e0 = (tid & 31) * 8;
    float acc[8][8];
#pragma unroll
    for (int a = 0; a < 8; a++)
#pragma unroll
        for (int b = 0; b < 8; b++) acc[a][b] = 0.f;

#pragma unroll 16
    for (int j = 0; j < 64; j++) {
        float a_[8];
#pragma unroll
        for (int r = 0; r < 8; r++) a_[r] = P[(ir + r) * 64 + j];
        float4 b0 = *(const float4*)&M2[j * 256 + e0];
        float4 b1 = *(const float4*)&M2[j * 256 + e0 + 4];
        float rb[8] = {b0.x, b0.y, b0.z, b0.w, b1.x, b1.y, b1.z, b1.w};
#pragma unroll
        for (int r = 0; r < 8; r++)
#pragma unroll
            for (int c = 0; c < 8; c++) acc[r][c] += a_[r] * rb[c];
    }

    const float* vb = g_Y + (long)n * QKV * SS + 512;
    float* ob = g_O + (long)n * SS * EE;
#pragma unroll
    for (int r = 0; r < 8; r++) {
        int i = i0g + ir + r;
        float4 v0 = *(const float4*)(vb + (long)i * QKV + e0);
        float4 v1 = *(const float4*)(vb + (long)i * QKV + e0 + 4);
        float4 o0 = make_float4(acc[r][0] + v0.x, acc[r][1] + v0.y, acc[r][2] + v0.z, acc[r][3] + v0.w);
        float4 o1 = make_float4(acc[r][4] + v1.x, acc[r][5] + v1.y, acc[r][6] + v1.z, acc[r][7] + v1.w);
        *(float4*)(ob + (long)i * 256 + e0) = o0;
        *(float4*)(ob + (long)i * 256 + e0 + 4) = o1;
    }
}

// ---------------- host ----------------
extern "C" void kernel_launch(void* const* d_in, const int* in_sizes, int n_in,
                              void* d_out, int out_size)
{
    const float* x     = (const float*)d_in[0];
    const float* w_qkv = (const float*)d_in[1];
    const float* b_qkv = (const float*)d_in[2];
    const float* w_out = (const float*)d_in[3];
    const float* b_out = (const float*)d_in[4];
    float* out = (float*)d_out;

    cudaFuncSetAttribute(k2inv_k, cudaFuncAttributeMaxDynamicSharedMemorySize,
                         K2INV_SMEM_FLOATS * (int)sizeof(float));
    cudaFuncSetAttribute(out_gemm_k, cudaFuncAttributeMaxDynamicSharedMemorySize,
                         OUT_SMEM_FLOATS * (int)sizeof(float));

    void *yb, *ob;
    cudaGetSymbolAddress(&yb, g_Y);
    cudaGetSymbolAddress(&ob, g_O);

    // 1) qkv projection: Y[n][768][4096] = w_qkv @ x[n] + b_qkv
    sgemm_bias_k<<<dim3(32, 6, NB), 256>>>(w_qkv, x, (float*)yb, b_qkv,
                                           QKV, SS, 256,
                                           (long)256 * SS, (long)QKV * SS);
    // 2) landmarks
    landmarks_k<<<dim3(NB, 64), 256>>>();
    // 3) S1 = q @ kland^T
    s1_gemm_k<<<dim3(64, NB), 256>>>();
    // 4) column softmax stats for k1
    colstats_part_k<<<dim3(8, NB), 256>>>();
    colstats_comb_k<<<NB, 64>>>();
    // 5) S3 = qland @ k^T, then softmax over landmarks
    s3_gemm_k<<<dim3(64, NB), 256>>>();
    softmax_s3_k<<<dim3(16, NB), 256>>>();
    // 6) T3 = k3 @ v (split-K + reduce)
    t3_splitk_k<<<dim3(32, NB), 256>>>();
    t3_reduce_k<<<512, 256>>>();
    // 7) k2 softmax + Newton-Schulz + M2s
    k2inv_k<<<NB, 1024, K2INV_SMEM_FLOATS * (int)sizeof(float)>>>();
    // 8) out = exp(S1-m) @ M2s + v
    out_gemm_k<<<dim3(64, NB), 256, OUT_SMEM_FLOATS * (int)sizeof(float)>>>();
    // 9) output projection: d_out[n][256][4096] = w_out @ O_view[n] + b_out
    sgemm_bias_k<<<dim3(32, 2, NB), 256>>>(w_out, (const float*)ob, out, b_out,
                                           256, SS, 256,
                                           (long)SS * EE, (long)256 * SS);
}

// round 5
// speedup vs baseline: 1.4345x; 1.4345x over previous
#include <cuda_runtime.h>
#include <cuda_bf16.h>
#include <cstdint>
#include <math.h>

#define NB   8
#define EE   256
#define LL   64
#define SS   4096
#define QKV  768

// ---------------- scratch ----------------
__device__ float g_Y[NB * QKV * SS];      // [n][e][s]; viewed as [n][s][768]
__device__ float g_qland[NB * LL * EE];
__device__ float g_kland[NB * LL * EE];
__device__ float g_S1[NB * SS * LL];
__device__ float g_pmax[NB * 8 * LL];
__device__ float g_psum[NB * 8 * LL];
__device__ float g_m[NB * LL];
__device__ float g_sinv[NB * LL];
__device__ float g_S3[NB * LL * SS];
__device__ float g_T3p[NB * 32 * LL * EE];
__device__ float g_T3[NB * LL * EE];
__device__ float g_M2s[NB * LL * EE];
__device__ float g_O[NB * SS * EE];       // [n][i][e]; viewed [n][256][4096]

// split-bf16 operands for tensor-core GEMMs
__device__ __nv_bfloat16 g_wqh[QKV * 256], g_wql[QKV * 256];
__device__ __nv_bfloat16 g_woh[256 * 256], g_wol[256 * 256];
__device__ __nv_bfloat16 g_xh[NB * SS * 256], g_xl[NB * SS * 256];   // [n][s][k]
__device__ __nv_bfloat16 g_oh[NB * SS * 256], g_ol[NB * SS * 256];   // [n][s][k]

__device__ __forceinline__ uint32_t smem_u32(const void* p) {
    uint32_t a;
    asm("{ .reg .u64 t; cvta.to.shared.u64 t, %1; cvt.u32.u64 %0, t; }" : "=r"(a) : "l"(p));
    return a;
}

__device__ __forceinline__ void mma_bf16(float* d, uint32_t a0, uint32_t a1, uint32_t a2,
                                         uint32_t a3, uint32_t b0, uint32_t b1) {
    asm volatile(
        "mma.sync.aligned.m16n8k16.row.col.f32.bf16.bf16.f32 "
        "{%0,%1,%2,%3}, {%4,%5,%6,%7}, {%8,%9}, {%0,%1,%2,%3};"
        : "+f"(d[0]), "+f"(d[1]), "+f"(d[2]), "+f"(d[3])
        : "r"(a0), "r"(a1), "r"(a2), "r"(a3), "r"(b0), "r"(b1));
}

// ================= split-bf16 mma.sync GEMM =================
// C[n][m][s] = sum_k (Ah+Al)[m][k]*(Bh+Bl)[n][s][k] + bias[m]   (lo*lo dropped)
// CTA tile 128(m) x 128(s), K=256 in 8 chunks of 32. Double-buffered cp.async.
// smem: 2 stages * 4 matrices(Ah,Al,Bh,Bl) * 128 rows * 80B (40 halves, 64B used)
#define MG_STAGE 40960
#define MG_SMEM  (2 * MG_STAGE)
__global__ __launch_bounds__(256, 2) void mma_gemm_k(
    const __nv_bfloat16* __restrict__ Ah, const __nv_bfloat16* __restrict__ Al,
    const __nv_bfloat16* __restrict__ Bh, const __nv_bfloat16* __restrict__ Bl,
    float* __restrict__ C, const float* __restrict__ bias,
    long bStride, long cStride)
{
    extern __shared__ char smc[];
    const int tid = threadIdx.x;
    const int lane = tid & 31, wid = tid >> 5;
    const int wm = wid >> 2, ws = wid & 3;         // warp grid 2 x 4
    const int gid = lane >> 2, tg = lane & 3;
    const int n = blockIdx.z;
    const int m0 = blockIdx.y * 128, s0 = blockIdx.x * 128;

    const __nv_bfloat16* gsrc[4];
    gsrc[0] = Ah + (long)m0 * 256;
    gsrc[1] = Al + (long)m0 * 256;
    gsrc[2] = Bh + (long)n * bStride + (long)s0 * 256;
    gsrc[3] = Bl + (long)n * bStride + (long)s0 * 256;

    float acc[4][4][4];
#pragma unroll
    for (int a = 0; a < 4; a++)
#pragma unroll
        for (int b = 0; b < 4; b++)
#pragma unroll
            for (int c = 0; c < 4; c++) acc[a][b][c] = 0.f;

    auto issue = [&](int c, int buf) {
#pragma unroll
        for (int it = 0; it < 8; it++) {
            int idx = tid + it * 256;
            int mat = idx >> 9, rr = (idx >> 2) & 127, seg = idx & 3;
            uint32_t d = smem_u32(smc + buf * MG_STAGE + mat * 10240 + rr * 80 + seg * 16);
            const __nv_bfloat16* s = gsrc[mat] + rr * 256 + c * 32 + seg * 8;
            asm volatile("cp.async.cg.shared.global [%0], [%1], 16;" :: "r"(d), "l"(s));
        }
        asm volatile("cp.async.commit_group;" ::: "memory");
    };

    issue(0, 0);
    for (int c = 0; c < 8; c++) {
        if (c < 7) {
            issue(c + 1, (c + 1) & 1);
            asm volatile("cp.async.wait_group 1;" ::: "memory");
        } else {
            asm volatile("cp.async.wait_group 0;" ::: "memory");
        }
        __syncthreads();
        const char* st = smc + (c & 1) * MG_STAGE;
#pragma unroll
        for (int ks = 0; ks < 2; ks++) {
            uint32_t bh[4][2], bl[4][2];
#pragma unroll
            for (int nt = 0; nt < 4; nt++) {
                int nrow = ws * 32 + nt * 8 + gid;
                const char* pb = st + 20480 + nrow * 80 + (ks * 16 + tg * 2) * 2;
                bh[nt][0] = *(const uint32_t*)pb;
                bh[nt][1] = *(const uint32_t*)(pb + 16);
                bl[nt][0] = *(const uint32_t*)(pb + 10240);
                bl[nt][1] = *(const uint32_t*)(pb + 10256);
            }
#pragma unroll
            for (int mt = 0; mt < 4; mt++) {
                int arow = wm * 64 + mt * 16 + gid;
                const char* pa = st + arow * 80 + (ks * 16 + tg * 2) * 2;
                uint32_t ah0 = *(const uint32_t*)pa;
                uint32_t ah1 = *(const uint32_t*)(pa + 640);
                uint32_t ah2 = *(const uint32_t*)(pa + 16);
                uint32_t ah3 = *(const uint32_t*)(pa + 656);
                uint32_t al0 = *(const uint32_t*)(pa + 10240);
                uint32_t al1 = *(const uint32_t*)(pa + 10880);
                uint32_t al2 = *(const uint32_t*)(pa + 10256);
                uint32_t al3 = *(const uint32_t*)(pa + 10896);
#pragma unroll
                for (int nt = 0; nt < 4; nt++) {
                    mma_bf16(acc[mt][nt], ah0, ah1, ah2, ah3, bh[nt][0], bh[nt][1]);
                    mma_bf16(acc[mt][nt], ah0, ah1, ah2, ah3, bl[nt][0], bl[nt][1]);
                    mma_bf16(acc[mt][nt], al0, al1, al2, al3, bh[nt][0], bh[nt][1]);
                }
            }
        }
        __syncthreads();
    }

    float* Cn = C + (long)n * cStride;
#pragma unroll
    for (int mt = 0; mt < 4; mt++) {
        int r0 = m0 + wm * 64 + mt * 16 + gid;
        float b0v = bias[r0], b1v = bias[r0 + 8];
#pragma unroll
        for (int nt = 0; nt < 4; nt++) {
            int col = s0 + ws * 32 + nt * 8 + tg * 2;
            float2 o0 = make_float2(acc[mt][nt][0] + b0v, acc[mt][nt][1] + b0v);
            float2 o1 = make_float2(acc[mt][nt][2] + b1v, acc[mt][nt][3] + b1v);
            *(float2*)(Cn + (long)r0 * 4096 + col) = o0;
            *(float2*)(Cn + (long)(r0 + 8) * 4096 + col) = o1;
        }
    }
}

// ---------------- converts ----------------
__global__ void cvt_w_k(const float* __restrict__ src, __nv_bfloat16* __restrict__ hi,
                        __nv_bfloat16* __restrict__ lo, int nElem)
{
    int i = blockIdx.x * 256 + threadIdx.x;
    if (i < nElem) {
        float v = src[i];
        __nv_bfloat16 h = __float2bfloat16(v);
        hi[i] = h;
        lo[i] = __float2bfloat16(v - __bfloat162float(h));
    }
}

// per batch: src [256][4096] fp32 row-major -> dst [4096][256] bf16 hi/lo
__global__ void tcvt_k(const float* __restrict__ src, __nv_bfloat16* __restrict__ hi,
                       __nv_bfloat16* __restrict__ lo)
{
    __shared__ float t[32][33];
    int n = blockIdx.z;
    const float* S = src + (long)n * 1048576;
    int s0 = blockIdx.x * 32, k0 = blockIdx.y * 32;
    int tx = threadIdx.x, ty = threadIdx.y;
#pragma unroll
    for (int i = 0; i < 32; i += 8) t[ty + i][tx] = S[(long)(k0 + ty + i) * 4096 + s0 + tx];
    __syncthreads();
    long base = (long)n * 1048576;
#pragma unroll
    for (int i = 0; i < 32; i += 8) {
        float v = t[tx][ty + i];
        __nv_bfloat16 h = __float2bfloat16(v);
        long o = base + (long)(s0 + ty + i) * 256 + k0 + tx;
        hi[o] = h;
        lo[o] = __float2bfloat16(v - __bfloat162float(h));
    }
}

// ---------------- landmarks ----------------
__global__ void landmarks_k()
{
    int n = blockIdx.x, l = blockIdx.y, e = threadIdx.x;
    const float* base = g_Y + (long)n * QKV * SS;
    float aq = 0.f, ak = 0.f;
#pragma unroll 4
    for (int r = 0; r < 64; r++) {
        long off = (long)(l * 64 + r) * QKV;
        aq += base[off + e];
        ak += base[off + 256 + e];
    }
    g_qland[(n * LL + l) * EE + e] = aq * (1.f / 4096.f);
    g_kland[(n * LL + l) * EE + e] = ak * (1.f / 4096.f);
}

// ---------------- S1 ----------------
__global__ __launch_bounds__(256) void s1_gemm_k()
{
    __shared__ float Qs[32][64];
    __shared__ float Ks[32][64];
    int n = blockIdx.y;
    int i0 = blockIdx.x * 64;
    const float* qb = g_Y + (long)n * QKV * SS;
    const float* kl = g_kland + n * LL * EE;
    int tid = threadIdx.x;
    int ti = tid >> 4, tj = tid & 15;
    int lr = tid >> 3;
    int lc = (tid & 7) * 4;
    float acc[4][4];
#pragma unroll
    for (int a = 0; a < 4; a++)
#pragma unroll
        for (int b = 0; b < 4; b++) acc[a][b] = 0.f;

    for (int e0 = 0; e0 < 256; e0 += 32) {
#pragma unroll
        for (int p = 0; p < 2; p++) {
            int row = lr + p * 32;
            float4 v = *(const float4*)(qb + (long)(i0 + row) * QKV + e0 + lc);
            Qs[lc + 0][row] = v.x; Qs[lc + 1][row] = v.y;
            Qs[lc + 2][row] = v.z; Qs[lc + 3][row] = v.w;
            float4 w = *(const float4*)(kl + row * EE + e0 + lc);
            Ks[lc + 0][row] = w.x; Ks[lc + 1][row] = w.y;
            Ks[lc + 2][row] = w.z; Ks[lc + 3][row] = w.w;
        }
        __syncthreads();
#pragma unroll
        for (int kk = 0; kk < 32; kk++) {
            float4 a = *(const float4*)&Qs[kk][ti * 4];
            float4 b = *(const float4*)&Ks[kk][tj * 4];
            float ra[4] = {a.x, a.y, a.z, a.w};
            float rb[4] = {b.x, b.y, b.z, b.w};
#pragma unroll
            for (int r = 0; r < 4; r++)
#pragma unroll
                for (int c = 0; c < 4; c++) acc[r][c] += ra[r] * rb[c];
        }
        __syncthreads();
    }
#pragma unroll
    for (int r = 0; r < 4; r++) {
        float4 o = make_float4(acc[r][0], acc[r][1], acc[r][2], acc[r][3]);
        *(float4*)(g_S1 + ((long)n * SS + i0 + ti * 4 + r) * 64 + tj * 4) = o;
    }
}

// ---------------- column softmax stats for S1 ----------------
__global__ void colstats_part_k()
{
    __shared__ float sm2[4][64];
    int stripe = blockIdx.x, n = blockIdx.y;
    int tid = threadIdx.x;
    int j = tid & 63, g = tid >> 6;
    const float* S = g_S1 + (long)n * SS * 64;
    float m = -1e30f;
    for (int i = stripe * 512 + g; i < stripe * 512 + 512; i += 4)
        m = fmaxf(m, S[(long)i * 64 + j]);
    sm2[g][j] = m;
    __syncthreads();
    float mm = fmaxf(fmaxf(sm2[0][j], sm2[1][j]), fmaxf(sm2[2][j], sm2[3][j]));
    float s = 0.f;
    for (int i = stripe * 512 + g; i < stripe * 512 + 512; i += 4)
        s += expf(S[(long)i * 64 + j] - mm);
    __syncthreads();
    sm2[g][j] = s;
    __syncthreads();
    if (g == 0) {
        float ss = sm2[0][j] + sm2[1][j] + sm2[2][j] + sm2[3][j];
        g_pmax[(n * 8 + stripe) * 64 + j] = mm;
        g_psum[(n * 8 + stripe) * 64 + j] = ss;
    }
}

__global__ void colstats_comb_k()
{
    int n = blockIdx.x, j = threadIdx.x;
    float m = -1e30f;
#pragma unroll
    for (int c = 0; c < 8; c++) m = fmaxf(m, g_pmax[(n * 8 + c) * 64 + j]);
    float s = 0.f;
#pragma unroll
    for (int c = 0; c < 8; c++)
        s += g_psum[(n * 8 + c) * 64 + j] * expf(g_pmax[(n * 8 + c) * 64 + j] - m);
    g_m[n * 64 + j] = m;
    g_sinv[n * 64 + j] = 1.f / s;
}

// ---------------- S3 ----------------
__global__ __launch_bounds__(256) void s3_gemm_k()
{
    __shared__ float Qs[32][64];
    __shared__ float Ks[32][64];
    int n = blockIdx.y;
    int s0 = blockIdx.x * 64;
    const float* ql = g_qland + n * LL * EE;
    const float* kb = g_Y + (long)n * QKV * SS + 256;
    int tid = threadIdx.x;
    int ti = tid >> 4, tj = tid & 15;
    int lr = tid >> 3;
    int lc = (tid & 7) * 4;
    float acc[4][4];
#pragma unroll
    for (int a = 0; a < 4; a++)
#pragma unroll
        for (int b = 0; b < 4; b++) acc[a][b] = 0.f;

    for (int e0 = 0; e0 < 256; e0 += 32) {
#pragma unroll
        for (int p = 0; p < 2; p++) {
            int row = lr + p * 32;
            float4 v = *(const float4*)(ql + row * EE + e0 + lc);
            Qs[lc + 0][row] = v.x; Qs[lc + 1][row] = v.y;
            Qs[lc + 2][row] = v.z; Qs[lc + 3][row] = v.w;
            float4 w = *(const float4*)(kb + (long)(s0 + row) * QKV + e0 + lc);
            Ks[lc + 0][row] = w.x; Ks[lc + 1][row] = w.y;
            Ks[lc + 2][row] = w.z; Ks[lc + 3][row] = w.w;
        }
        __syncthreads();
#pragma unroll
        for (int kk = 0; kk < 32; kk++) {
            float4 a = *(const float4*)&Qs[kk][ti * 4];
            float4 b = *(const float4*)&Ks[kk][tj * 4];
            float ra[4] = {a.x, a.y, a.z, a.w};
            float rb[4] = {b.x, b.y, b.z, b.w};
#pragma unroll
            for (int r = 0; r < 4; r++)
#pragma unroll
                for (int c = 0; c < 4; c++) acc[r][c] += ra[r] * rb[c];
        }
        __syncthreads();
    }
#pragma unroll
    for (int r = 0; r < 4; r++) {
        float4 o = make_float4(acc[r][0], acc[r][1], acc[r][2], acc[r][3]);
        *(float4*)(g_S3 + ((long)n * LL + ti * 4 + r) * SS + s0 + tj * 4) = o;
    }
}

__global__ void softmax_s3_k()
{
    int n = blockIdx.y;
    int s = blockIdx.x * 256 + threadIdx.x;
    float* S = g_S3 + (long)n * LL * SS;
    float v[64];
    float m = -1e30f;
#pragma unroll
    for (int j = 0; j < 64; j++) { v[j] = S[(long)j * SS + s]; m = fmaxf(m, v[j]); }
    float sum = 0.f;
#pragma unroll
    for (int j = 0; j < 64; j++) { v[j] = expf(v[j] - m); sum += v[j]; }
    float r = 1.f / sum;
#pragma unroll
    for (int j = 0; j < 64; j++) S[(long)j * SS + s] = v[j] * r;
}

// ---------------- T3 = k3 @ v ----------------
__global__ __launch_bounds__(256) void t3_splitk_k()
{
    __shared__ float As[16][64];
    __shared__ float Vs[16][256];
    int ch = blockIdx.x, n = blockIdx.y;
    int s0 = ch * 128;
    const float* S = g_S3 + (long)n * LL * SS;
    const float* vb = g_Y + (long)n * QKV * SS + 512;
    int tid = threadIdx.x;
    int j0 = (tid >> 5) * 8, e0 = (tid & 31) * 8;
    int ajr = tid >> 2;
    int asc = (tid & 3) * 4;
    int vr = tid >> 4;
    int vc = (tid & 15) * 4;

    float acc[8][8];
#pragma unroll
    for (int a = 0; a < 8; a++)
#pragma unroll
        for (int b = 0; b < 8; b++) acc[a][b] = 0.f;

    for (int sb = 0; sb < 128; sb += 16) {
        float4 a = *(const float4*)(S + (long)ajr * SS + s0 + sb + asc);
        As[asc + 0][ajr] = a.x; As[asc + 1][ajr] = a.y;
        As[asc + 2][ajr] = a.z; As[asc + 3][ajr] = a.w;
#pragma unroll
        for (int p = 0; p < 4; p++)
            *(float4*)&Vs[vr][vc + p * 64] =
                *(const float4*)(vb + (long)(s0 + sb + vr) * QKV + vc + p * 64);
        __syncthreads();
#pragma unroll
        for (int sc = 0; sc < 16; sc++) {
            float a_[8];
#pragma unroll
            for (int r = 0; r < 8; r++) a_[r] = As[sc][j0 + r];
            float4 b0 = *(const float4*)&Vs[sc][e0];
            float4 b1 = *(const float4*)&Vs[sc][e0 + 4];
            float rb[8] = {b0.x, b0.y, b0.z, b0.w, b1.x, b1.y, b1.z, b1.w};
#pragma unroll
            for (int r = 0; r < 8; r++)
#pragma unroll
                for (int c = 0; c < 8; c++) acc[r][c] += a_[r] * rb[c];
        }
        __syncthreads();
    }
    float* dst = g_T3p + (long)(n * 32 + ch) * 64 * 256;
#pragma unroll
    for (int r = 0; r < 8; r++) {
        float4 o0 = make_float4(acc[r][0], acc[r][1], acc[r][2], acc[r][3]);
        float4 o1 = make_float4(acc[r][4], acc[r][5], acc[r][6], acc[r][7]);
        *(float4*)(dst + (j0 + r) * 256 + e0) = o0;
        *(float4*)(dst + (j0 + r) * 256 + e0 + 4) = o1;
    }
}

__global__ void t3_reduce_k()
{
    int idx = blockIdx.x * 256 + threadIdx.x;
    int n = idx >> 14;
    int r = idx & 16383;
    const float* p = g_T3p + (long)n * 32 * 16384 + r;
    float s = 0.f;
#pragma unroll
    for (int c = 0; c < 32; c++) s += p[(long)c * 16384];
    g_T3[idx] = s;
}

// ---------------- 64x64 smem matmul helper ----------------
__device__ __forceinline__ void mm64(float* D, const float* A, const float* B, int tid)
{
    int r = (tid >> 5) * 2;
    int c = (tid & 31) * 2;
    float d00 = 0.f, d01 = 0.f, d10 = 0.f, d11 = 0.f;
#pragma unroll 16
    for (int k = 0; k < 64; k++) {
        float a0 = A[r * 64 + k], a1 = A[(r + 1) * 64 + k];
        float b0 = B[k * 64 + c], b1 = B[k * 64 + c + 1];
        d00 += a0 * b0; d01 += a0 * b1; d10 += a1 * b0; d11 += a1 * b1;
    }
    D[r * 64 + c] = d00; D[r * 64 + c + 1] = d01;
    D[(r + 1) * 64 + c] = d10; D[(r + 1) * 64 + c + 1] = d11;
    __syncthreads();
}

// ---------------- k2 softmax + Newton-Schulz + M2s ----------------
#define K2INV_SMEM_FLOATS (4096 * 5 + 2048 * 2 + 192)
__global__ __launch_bounds__(1024) void k2inv_k()
{
    extern __shared__ float sm[];
    float* K2 = sm;
    float* Vv = sm + 4096;
    float* BA = sm + 8192;
    float* BB = sm + 12288;
    float* BC = sm + 16384;
    float* QL = sm + 20480;
    float* KT = sm + 22528;
    float* red = sm + 24576;

    int n = blockIdx.x;
    int tid = threadIdx.x;
    const float* ql = g_qland + n * 16384;
    const float* kl = g_kland + n * 16384;

    float accS[4] = {0.f, 0.f, 0.f, 0.f};
    for (int e0 = 0; e0 < 256; e0 += 32) {
#pragma unroll
        for (int p = 0; p < 2; p++) {
            int t = tid + p * 1024;
            int r = t >> 5, c = t & 31;
            QL[r * 32 + c] = ql[r * 256 + e0 + c];
            KT[c * 64 + r] = kl[r * 256 + e0 + c];
        }
        __syncthreads();
#pragma unroll
        for (int p = 0; p < 4; p++) {
            int t = tid + p * 1024;
            int i = t >> 6, j = t & 63;
            float a = 0.f;
#pragma unroll
            for (int ec = 0; ec < 32; ec++) a += QL[i * 32 + ec] * KT[ec * 64 + j];
            accS[p] += a;
        }
        __syncthreads();
    }
#pragma unroll
    for (int p = 0; p < 4; p++) K2[tid + p * 1024] = accS[p];
    __syncthreads();

    if (tid < 64) {
        int j = tid;
        float m = -1e30f;
        for (int i = 0; i < 64; i++) m = fmaxf(m, K2[i * 64 + j]);
        float s = 0.f;
        for (int i = 0; i < 64; i++) s += expf(K2[i * 64 + j] - m);
        red[j] = m; red[64 + j] = 1.f / s;
    }
    __syncthreads();
#pragma unroll
    for (int p = 0; p < 4; p++) {
        int t = tid + p * 1024;
        int j = t & 63;
        K2[t] = expf(K2[t] - red[j]) * red[64 + j];
    }
    __syncthreads();

    if (tid < 64) {
        int i = tid;
        float rs = 0.f, cs = 0.f;
        for (int j = 0; j < 64; j++) { rs += fabsf(K2[i * 64 + j]); cs += fabsf(K2[j * 64 + i]); }
        red[i] = rs; red[64 + i] = cs;
    }
    __syncthreads();
    if (tid == 0) {
        float vi = 0.f, v0 = 0.f;
        for (int t = 0; t < 64; t++) { vi = fmaxf(vi, red[t]); v0 = fmaxf(v0, red[64 + t]); }
        red[128] = 1.f / (v0 * vi);
    }
    __syncthreads();
    float isc = red[128];
#pragma unroll
    for (int p = 0; p < 4; p++) {
        int t = tid + p * 1024;
        int a = t >> 6, b = t & 63;
        Vv[t] = K2[b * 64 + a] * isc;
    }
    __syncthreads();

    for (int it = 0; it < 6; it++) {
        mm64(BA, K2, Vv, tid);
        mm64(BB, BA, BA, tid);
#pragma unroll
        for (int p = 0; p < 4; p++) {
            int t = tid + p * 1024;
            float d = ((t >> 6) == (t & 63)) ? 15.f : 0.f;
            BB[t] = d - 7.f * BA[t] + BB[t];
        }
        __syncthreads();
        mm64(BC, BA, BB, tid);
#pragma unroll
        for (int p = 0; p < 4; p++) {
            int t = tid + p * 1024;
            float d = ((t >> 6) == (t & 63)) ? 13.f : 0.f;
            BC[t] = d - BC[t];
        }
        __syncthreads();
        mm64(BB, Vv, BC, tid);
#pragma unroll
        for (int p = 0; p < 4; p++) {
            int t = tid + p * 1024;
            Vv[t] = 0.25f * BB[t];
        }
        __syncthreads();
    }

    const float* T3 = g_T3 + n * 16384;
    for (int t = tid; t < 16384; t += 1024) {
        int j = t >> 8, e = t & 255;
        float a = 0.f;
#pragma unroll
        for (int k = 0; k < 64; k++) a += Vv[j * 64 + k] * T3[k * 256 + e];
        g_M2s[n * 16384 + t] = a * g_sinv[n * 64 + j];
    }
}

// ---------------- out = exp(S1 - m) @ M2s + v ----------------
#define OUT_SMEM_FLOATS (16384 + 4096 + 64)
__global__ __launch_bounds__(256) void out_gemm_k()
{
    extern __shared__ float sm[];
    float* M2 = sm;
    float* P  = sm + 16384;
    float* ms = sm + 20480;
    int n = blockIdx.y;
    int i0g = blockIdx.x * 64;
    int tid = threadIdx.x;

    for (int t = tid * 4; t < 16384; t += 1024)
        *(float4*)&M2[t] = *(const float4*)(g_M2s + n * 16384 + t);
    if (tid < 64) ms[tid] = g_m[n * 64 + tid];
    __syncthreads();

    {
        int r = tid >> 2, c0 = (tid & 3) * 16;
        const float* S = g_S1 + ((long)n * SS + i0g + r) * 64 + c0;
#pragma unroll
        for (int t = 0; t < 16; t += 4) {
            float4 v = *(const float4*)(S + t);
            P[r * 64 + c0 + t + 0] = expf(v.x - ms[c0 + t + 0]);
            P[r * 64 + c0 + t + 1] = expf(v.y - ms[c0 + t + 1]);
            P[r * 64 + c0 + t + 2] = expf(v.z - ms[c0 + t + 2]);
            P[r * 64 + c0 + t + 3] = expf(v.w - ms[c0 + t + 3]);
        }
    }
    __syncthreads();

    int ir = (tid >> 5) * 8, e0 = (tid & 31) * 8;
    float acc[8][8];
#pragma unroll
    for (int a = 0; a < 8; a++)
#pragma unroll
        for (int b = 0; b < 8; b++) acc[a][b] = 0.f;

#pragma unroll 16
    for (int j = 0; j < 64; j++) {
        float a_[8];
#pragma unroll
        for (int r = 0; r < 8; r++) a_[r] = P[(ir + r) * 64 + j];
        float4 b0 = *(const float4*)&M2[j * 256 + e0];
        float4 b1 = *(const float4*)&M2[j * 256 + e0 + 4];
        float rb[8] = {b0.x, b0.y, b0.z, b0.w, b1.x, b1.y, b1.z, b1.w};
#pragma unroll
        for (int r = 0; r < 8; r++)
#pragma unroll
            for (int c = 0; c < 8; c++) acc[r][c] += a_[r] * rb[c];
    }

    const float* vb = g_Y + (long)n * QKV * SS + 512;
    float* ob = g_O + (long)n * SS * EE;
#pragma unroll
    for (int r = 0; r < 8; r++) {
        int i = i0g + ir + r;
        float4 v0 = *(const float4*)(vb + (long)i * QKV + e0);
        float4 v1 = *(const float4*)(vb + (long)i * QKV + e0 + 4);
        float4 o0 = make_float4(acc[r][0] + v0.x, acc[r][1] + v0.y, acc[r][2] + v0.z, acc[r][3] + v0.w);
        float4 o1 = make_float4(acc[r][4] + v1.x, acc[r][5] + v1.y, acc[r][6] + v1.z, acc[r][7] + v1.w);
        *(float4*)(ob + (long)i * 256 + e0) = o0;
        *(float4*)(ob + (long)i * 256 + e0 + 4) = o1;
    }
}

// ---------------- host ----------------
extern "C" void kernel_launch(void* const* d_in, const int* in_sizes, int n_in,
                              void* d_out, int out_size)
{
    const float* x     = (const float*)d_in[0];
    const float* w_qkv = (const float*)d_in[1];
    const float* b_qkv = (const float*)d_in[2];
    const float* w_out = (const float*)d_in[3];
    const float* b_out = (const float*)d_in[4];
    float* out = (float*)d_out;

    cudaFuncSetAttribute(k2inv_k, cudaFuncAttributeMaxDynamicSharedMemorySize,
                         K2INV_SMEM_FLOATS * (int)sizeof(float));
    cudaFuncSetAttribute(out_gemm_k, cudaFuncAttributeMaxDynamicSharedMemorySize,
                         OUT_SMEM_FLOATS * (int)sizeof(float));
    cudaFuncSetAttribute(mma_gemm_k, cudaFuncAttributeMaxDynamicSharedMemorySize, MG_SMEM);

    void *yb, *ob;
    cudaGetSymbolAddress(&yb, g_Y);
    cudaGetSymbolAddress(&ob, g_O);
    void *wqh, *wql, *woh, *wol, *xh, *xl, *oh, *ol;
    cudaGetSymbolAddress(&wqh, g_wqh); cudaGetSymbolAddress(&wql, g_wql);
    cudaGetSymbolAddress(&woh, g_woh); cudaGetSymbolAddress(&wol, g_wol);
    cudaGetSymbolAddress(&xh, g_xh);   cudaGetSymbolAddress(&xl, g_xl);
    cudaGetSymbolAddress(&oh, g_oh);   cudaGetSymbolAddress(&ol, g_ol);

    // 0) operand conversion
    cvt_w_k<<<768, 256>>>(w_qkv, (__nv_bfloat16*)wqh, (__nv_bfloat16*)wql, QKV * 256);
    cvt_w_k<<<256, 256>>>(w_out, (__nv_bfloat16*)woh, (__nv_bfloat16*)wol, 256 * 256);
    tcvt_k<<<dim3(128, 8, NB), dim3(32, 8)>>>(x, (__nv_bfloat16*)xh, (__nv_bfloat16*)xl);

    // 1) qkv projection (mma.sync): Y[n][768][4096] = w_qkv @ x[n] + b_qkv
    mma_gemm_k<<<dim3(32, 6, NB), 256, MG_SMEM>>>(
        (const __nv_bfloat16*)wqh, (const __nv_bfloat16*)wql,
        (const __nv_bfloat16*)xh, (const __nv_bfloat16*)xl,
        (float*)yb, b_qkv, (long)SS * 256, (long)QKV * SS);

    // 2..8) attention pipeline
    landmarks_k<<<dim3(NB, 64), 256>>>();
    s1_gemm_k<<<dim3(64, NB), 256>>>();
    colstats_part_k<<<dim3(8, NB), 256>>>();
    colstats_comb_k<<<NB, 64>>>();
    s3_gemm_k<<<dim3(64, NB), 256>>>();
    softmax_s3_k<<<dim3(16, NB), 256>>>();
    t3_splitk_k<<<dim3(32, NB), 256>>>();
    t3_reduce_k<<<512, 256>>>();
    k2inv_k<<<NB, 1024, K2INV_SMEM_FLOATS * (int)sizeof(float)>>>();
    out_gemm_k<<<dim3(64, NB), 256, OUT_SMEM_FLOATS * (int)sizeof(float)>>>();

    // 9) output projection (mma.sync): d_out[n][256][4096] = w_out @ O_view[n] + b_out
    tcvt_k<<<dim3(128, 8, NB), dim3(32, 8)>>>((const float*)ob, (__nv_bfloat16*)oh, (__nv_bfloat16*)ol);
    mma_gemm_k<<<dim3(32, 2, NB), 256, MG_SMEM>>>(
        (const __nv_bfloat16*)woh, (const __nv_bfloat16*)wol,
        (const __nv_bfloat16*)oh, (const __nv_bfloat16*)ol,
        out, b_out, (long)SS * 256, (long)256 * SS);
}